// round 17
// baseline (speedup 1.0000x reference)
#include <cuda_runtime.h>

#define NB       32
#define NPTS     16384
#define SGRID    768
#define GOUT     256
#define SLICES   4
#define RPS      64                         // output rows per slice
#define THREADS  512
#define ITERS    (NPTS / THREADS)           // 32 points per thread
#define OUT_HALF ((size_t)NB * GOUT * GOUT * 3)   // 6,291,456 floats
#define SLICE_F  (RPS * GOUT * 3)           // 49,152 floats = 192 KB
#define SMEM_BYTES (SLICE_F * sizeof(float))

// Correctly-rounded e/3 without MUFU: Markstein refinement from c = RN(1/3).
// q0 within 1 ulp; r = e - 3*q0 exact via FMA; q = RN(q0 + r*c) == RN(e/3).
__device__ __forceinline__ float div3_rn(float e) {
    const float c = 0.33333334f;             // RN(1/3) = 0x3EAAAAAB
    float q0 = __fmul_rn(e, c);
    float r  = __fmaf_rn(-3.0f, q0, e);
    return __fmaf_rn(r, c, q0);
}

// One block = (batch b, r-slice s). The block recomputes ALL of batch b's
// lattice coords (register-resident), so its local min over all points IS the
// batch offset -> no cross-block communication, single kernel node.
// Splat goes to a 64x256x3 SMEM tile via shared atomics, then bulk STG to both
// output copies (covers zero cells too -> no output pre-zeroing, no copy pass).
__global__ void __launch_bounds__(THREADS)
splat_kernel(const float* __restrict__ pc, const float* __restrict__ feat,
             float* __restrict__ out, int dual)
{
    extern __shared__ float sm[];            // 49152 floats: [(r&63)*768 + c*3 + ch]
    const int bid = blockIdx.x;
    const int b   = bid / SLICES;
    const int s   = bid % SLICES;
    const int t   = threadIdx.x;

    // ---- pass 1: lattice coords for all 16K points of batch b ----
    const float S6 = (float)2.449489742783178;      // np.float32(np.sqrt(6.0))
    const float A  = __fdiv_rn(2.0f, S6);
    const float C  = __fdiv_rn(-1.0f, S6);

    const float* p = pc + (size_t)b * 3 * NPTS;
    int glreg[ITERS];                        // packed (gi0, gi1), fully unrolled
    int k0 = 0x7FFFFFFF, k1 = 0x7FFFFFFF;

    #pragma unroll
    for (int i = 0; i < ITERS; i++) {
        const int n = i * THREADS + t;
        float p0 = p[n];
        float p1 = p[n + NPTS];
        float p2 = p[n + 2 * NPTS];

        // cuBLAS-style K-ascending FMA chain (bit-exact vs XLA dot)
        float e0 = __fmaf_rn(C, p2, __fmaf_rn(C, p1, __fmul_rn(A, p0)));
        float e1 = __fmaf_rn(C, p2, __fmaf_rn(A, p1, __fmul_rn(C, p0)));
        float e2 = __fmaf_rn(A, p2, __fmaf_rn(C, p1, __fmul_rn(C, p0)));

        // greedy = rint(RN(e/3))*3  (rintf = half-even, matches jnp.round)
        float g0 = __fmul_rn(rintf(div3_rn(e0)), 3.0f);
        float g1 = __fmul_rn(rintf(div3_rn(e1)), 3.0f);
        float g2 = __fmul_rn(rintf(div3_rn(e2)), 3.0f);
        float m0 = __fadd_rn(e0, -g0);
        float m1 = __fadd_rn(e1, -g1);
        float m2 = __fadd_rn(e2, -g2);

        // rank: stable descending sort semantics (ties -> lower index first)
        int r0 = (m1 > m0) + (m2 > m0);
        int r1 = (m0 >= m1) + (m2 > m1);

        int gi0 = (int)g0;
        int gi1 = (int)g1;
        int gi2 = (int)g2;
        int rs  = (gi0 + gi1 + gi2) / 3;     // exact: sum of multiples of 3

        int sg = 0, c0 = 0, c1 = 0;
        if (rs > 0)      { sg = -1; c0 = (r0 >= 3 - rs); c1 = (r1 >= 3 - rs); }
        else if (rs < 0) { sg =  1; c0 = (r0 < -rs);     c1 = (r1 < -rs);     }
        gi0 += 3 * sg * c0;
        gi1 += 3 * sg * c1;
        r0  += 3 * sg * c0 + rs;
        r1  += 3 * sg * c1 + rs;

        glreg[i] = (gi0 & 0xFFFF) | (gi1 << 16);

        // min_j key component = gl - rank (rank in [0,2] after correction).
        // Offset min is over ALL points (OOB drop applies only to the scatter).
        k0 = min(k0, gi0 - r0);
        k1 = min(k1, gi1 - r1);
    }

    k0 = __reduce_min_sync(0xFFFFFFFF, k0);  // REDUX.MIN
    k1 = __reduce_min_sync(0xFFFFFFFF, k1);

    __shared__ int sr0[THREADS / 32], sr1[THREADS / 32];
    const int wid = t >> 5;
    if ((t & 31) == 0) { sr0[wid] = k0; sr1[wid] = k1; }

    // ---- zero the SMEM tile (same barrier covers minima + zeros) ----
    {
        float4 z = make_float4(0.f, 0.f, 0.f, 0.f);
        float4* smv = (float4*)sm;
        #pragma unroll
        for (int j = 0; j < SLICE_F / 4 / THREADS; j++)   // 24 stores
            smv[j * THREADS + t] = z;
    }
    __syncthreads();

    int off0 = sr0[0], off1 = sr1[0];
    #pragma unroll
    for (int w = 1; w < THREADS / 32; w++) {
        off0 = min(off0, sr0[w]);
        off1 = min(off1, sr1[w]);
    }
    const int pick0 = ((-off0) % 3 + 3) % 3;
    const int pick1 = ((-off1) % 3 + 3) % 3;

    // ---- pass 2: splat into the SMEM tile (bary == [1,0,0] -> vertex 0) ----
    const float* f = feat + (size_t)b * 3 * NPTS;
    #pragma unroll
    for (int i = 0; i < ITERS; i++) {
        const int n = i * THREADS + t;
        int v   = glreg[i];
        int gl0 = (int)(short)(v & 0xFFFF);
        int gl1 = v >> 16;                   // arithmetic shift sign-extends
        int x0 = gl0 - off0;                 // >= 0 by construction
        int x1 = gl1 - off1;
        if (x0 < SGRID && x1 < SGRID) {      // JAX scatter drops OOB
            int r = (x0 - pick0) / 3;        // exact: x ≡ pick (mod 3)
            if ((r >> 6) == s) {             // this block's 64-row slice
                int c = (x1 - pick1) / 3;
                float* cell = sm + (r & (RPS - 1)) * (GOUT * 3) + c * 3;
                atomicAdd(cell + 0, f[n]);
                atomicAdd(cell + 1, f[n + NPTS]);
                atomicAdd(cell + 2, f[n + 2 * NPTS]);
            }
        }
    }
    __syncthreads();

    // ---- write the tile to both output copies (contiguous 192 KB) ----
    {
        const float4* smv = (const float4*)sm;
        float4* d0 = (float4*)(out + (size_t)b * (GOUT * GOUT * 3) + (size_t)s * SLICE_F);
        #pragma unroll
        for (int j = 0; j < SLICE_F / 4 / THREADS; j++) {  // 24 stores
            int idx = j * THREADS + t;
            d0[idx] = smv[idx];
        }
        if (dual) {
            float4* d1 = (float4*)(out + OUT_HALF + (size_t)b * (GOUT * GOUT * 3) + (size_t)s * SLICE_F);
            #pragma unroll
            for (int j = 0; j < SLICE_F / 4 / THREADS; j++) {
                int idx = j * THREADS + t;
                d1[idx] = smv[idx];
            }
        }
    }
}

extern "C" void kernel_launch(void* const* d_in, const int* in_sizes, int n_in,
                              void* d_out, int out_size) {
    const float* pc   = (const float*)d_in[0];
    const float* feat = (const float*)d_in[1];
    float* out = (float*)d_out;
    int dual = ((size_t)out_size >= 2 * OUT_HALF) ? 1 : 0;

    cudaFuncSetAttribute(splat_kernel,
                         cudaFuncAttributeMaxDynamicSharedMemorySize, SMEM_BYTES);
    splat_kernel<<<NB * SLICES, THREADS, SMEM_BYTES>>>(pc, feat, out, dual);
}